// round 13
// baseline (speedup 1.0000x reference)
#include <cuda_runtime.h>
#include <cuda_fp16.h>
#include <cstdint>

#define NN 50000
#define EE 800000
#define RR 16
#define CC 128
#define K1 2048            // R*C
#define YN 2176            // K1 + C  (Y = X @ [W_all | root])
#define NT 17              // YN / 128 n-tiles
#define EPS 1e-5f

// smem geometry for GEMM tiles: 128 x 136 fp16 (word stride 68 -> conflict-free)
#define ABYTES (128 * 136 * 2)     // 34816 bytes per tile array
#define GEMM_SMEM (3 * ABYTES)     // A + 2 stages x B = 104448

// ---------------- scratch ----------------
__device__ __half    g_Yh[(size_t)NN * YN];  // transformed features (fp16)
__device__ float    g_h[(size_t)NN * CC];    // hidden activations (pre-BN)
__device__ uint32_t g_ax[NN * 64];           // A operand fp16 (pairs), 256B rows
__device__ __half   g_bh[2 * YN * CC];       // packed B fp16 (both layers), [n][k]
__device__ int   g_cnt[NN * RR];
__device__ float g_winv[NN * RR];
__device__ int   g_deg[NN];
__device__ int   g_rowptr[NN];
__device__ int   g_cursor[NN];
__device__ int   g_bsumscan[64];
__device__ int   g_edge[EE];                 // sorted-by-dst: src | (rel<<20)
__device__ float g_bnsum[CC];
__device__ float g_bnsq[CC];
__device__ float g_scale[CC];
__device__ float g_shift[CC];

// ---------------- small helpers ----------------
__device__ __forceinline__ void cp16(uint32_t dst, const void* src) {
    asm volatile("cp.async.cg.shared.global [%0], [%1], 16;" :: "r"(dst), "l"(src));
}
__device__ __forceinline__ void cp_commit() { asm volatile("cp.async.commit_group;"); }

__device__ __forceinline__ void mma16816h(float* c, const uint32_t* a, const uint32_t* b) {
    asm volatile("mma.sync.aligned.m16n8k16.row.col.f32.f16.f16.f32 "
        "{%0,%1,%2,%3}, {%4,%5,%6,%7}, {%8,%9}, {%0,%1,%2,%3};"
        : "+f"(c[0]), "+f"(c[1]), "+f"(c[2]), "+f"(c[3])
        : "r"(a[0]), "r"(a[1]), "r"(a[2]), "r"(a[3]), "r"(b[0]), "r"(b[1]));
}

// ---------------- structure prep ----------------
__global__ void k_init() {
    int i = blockIdx.x * blockDim.x + threadIdx.x;
    if (i < NN * RR) g_cnt[i] = 0;
    if (i < CC) { g_bnsum[i] = 0.f; g_bnsq[i] = 0.f; }
}
__global__ void k_count(const int* __restrict__ ei, const int* __restrict__ et) {
    int e = blockIdx.x * blockDim.x + threadIdx.x;
    if (e >= EE) return;
    int dst = ei[EE + e];
    int r = et[e]; if (r > RR - 1) r = RR - 1;
    atomicAdd(&g_cnt[dst * RR + r], 1);
}
__global__ void k_winv_deg() {
    int n = blockIdx.x * blockDim.x + threadIdx.x;
    if (n >= NN) return;
    int d = 0;
    #pragma unroll
    for (int r = 0; r < RR; r++) {
        int c = g_cnt[n * RR + r];
        d += c;
        g_winv[n * RR + r] = 1.0f / (float)(c > 0 ? c : 1);
    }
    g_deg[n] = d;
}
__global__ void k_scan1() {   // 49 blocks x 1024
    __shared__ int sh[1024];
    int t = threadIdx.x;
    int idx = blockIdx.x * 1024 + t;
    int v = (idx < NN) ? g_deg[idx] : 0;
    sh[t] = v;
    __syncthreads();
    for (int o = 1; o < 1024; o <<= 1) {
        int add = (t >= o) ? sh[t - o] : 0;
        __syncthreads();
        sh[t] += add;
        __syncthreads();
    }
    if (idx < NN) g_rowptr[idx] = sh[t] - v;
    if (t == 1023) g_bsumscan[blockIdx.x] = sh[t];
}
__global__ void k_scan2() {
    if (threadIdx.x == 0) {
        int acc = 0;
        for (int b = 0; b < 49; b++) { int v = g_bsumscan[b]; g_bsumscan[b] = acc; acc += v; }
    }
}
__global__ void k_scan3() {
    int idx = blockIdx.x * blockDim.x + threadIdx.x;
    if (idx >= NN) return;
    int p = g_rowptr[idx] + g_bsumscan[idx >> 10];
    g_rowptr[idx] = p;
    g_cursor[idx] = p;
}
__global__ void k_place(const int* __restrict__ ei, const int* __restrict__ et) {
    int e = blockIdx.x * blockDim.x + threadIdx.x;
    if (e >= EE) return;
    int src = ei[e];
    int dst = ei[EE + e];
    int r = et[e]; if (r > RR - 1) r = RR - 1;
    int pos = atomicAdd(&g_cursor[dst], 1);
    g_edge[pos] = src | (r << 20);
}

// ---------------- operand prep ----------------
__global__ void k_packB(const float* __restrict__ W, const float* __restrict__ root,
                        __half* __restrict__ bh) {
    int idx = blockIdx.x * blockDim.x + threadIdx.x;   // n*128 + k
    if (idx >= YN * CC) return;
    int n = idx >> 7, k = idx & 127;
    float v = (n < K1) ? W[((size_t)(n >> 7) << 14) + (k << 7) + (n & 127)]
                       : root[(k << 7) + (n - K1)];
    bh[idx] = __float2half_rn(v);
}
__global__ void k_packX(const float* __restrict__ x) {
    int i = blockIdx.x * blockDim.x + threadIdx.x;     // float2 units
    if (i >= NN * 64) return;
    float2 v = ((const float2*)x)[i];
    __half2 h = __floats2half2_rn(v.x, v.y);
    g_ax[i] = *(uint32_t*)&h;
}

// =====================================================================
// GEMM: Y[N, 2176] = A[N,128] @ B^T   (fp16 x fp16, fp32 accum)
// =====================================================================
__global__ __launch_bounds__(256, 2) void k_gemm(
    const __half* __restrict__ Ahg,
    const __half* __restrict__ Bhg,   // [2176][128] n-major
    __half* __restrict__ Y)
{
    extern __shared__ char smem[];
    const int tid = threadIdx.x, lane = tid & 31, wid = tid >> 5;
    const int g = lane >> 2, tg = lane & 3;
    const int warpRow = (wid & 3) * 32, warpCol = (wid >> 2) * 64;
    const int m0 = blockIdx.x * 128;
    uint32_t sb = (uint32_t)__cvta_generic_to_shared(smem);

    #pragma unroll
    for (int it = 0; it < 8; it++) {
        int c = tid + it * 256;
        int row = c >> 4, chk = c & 15;
        int gr = m0 + row;
        if (gr >= NN) gr = NN - 1;
        size_t off = (size_t)gr * CC + chk * 8;
        cp16(sb + row * 272 + chk * 16, Ahg + off);
    }
    auto loadB = [&](int stage, int nt) {
        uint32_t bb = sb + ABYTES + stage * ABYTES;
        #pragma unroll
        for (int it = 0; it < 8; it++) {
            int c = tid + it * 256;
            int row = c >> 4, chk = c & 15;
            size_t goff = (size_t)(nt * CC + row) * CC + chk * 8;
            cp16(bb + row * 272 + chk * 16, Bhg + goff);
        }
    };
    loadB(0, 0);
    cp_commit();

    const uint32_t* A32 = (const uint32_t*)smem;

    for (int nt = 0; nt < NT; nt++) {
        int cur = nt & 1;
        if (nt + 1 < NT) {
            loadB(cur ^ 1, nt + 1);
            cp_commit();
            asm volatile("cp.async.wait_group 1;");
        } else {
            asm volatile("cp.async.wait_group 0;");
        }
        __syncthreads();

        const uint32_t* B32 = (const uint32_t*)(smem + ABYTES + cur * ABYTES);

        float acc[2][8][4];
        #pragma unroll
        for (int mi = 0; mi < 2; mi++)
            #pragma unroll
            for (int ni = 0; ni < 8; ni++)
                #pragma unroll
                for (int q = 0; q < 4; q++) acc[mi][ni][q] = 0.f;

        #pragma unroll
        for (int ks = 0; ks < 8; ks++) {
            int kp = ks * 8;
            uint32_t ah[2][4];
            #pragma unroll
            for (int mi = 0; mi < 2; mi++) {
                int r = warpRow + mi * 16 + g;
                ah[mi][0] = A32[r * 68 + kp + tg];
                ah[mi][1] = A32[(r + 8) * 68 + kp + tg];
                ah[mi][2] = A32[r * 68 + kp + tg + 4];
                ah[mi][3] = A32[(r + 8) * 68 + kp + tg + 4];
            }
            #pragma unroll
            for (int ni = 0; ni < 8; ni++) {
                int n = warpCol + ni * 8 + g;
                uint32_t bh[2] = { B32[n * 68 + kp + tg], B32[n * 68 + kp + tg + 4] };
                mma16816h(acc[0][ni], ah[0], bh);
                mma16816h(acc[1][ni], ah[1], bh);
            }
        }

        #pragma unroll
        for (int ni = 0; ni < 8; ni++) {
            int col = nt * 128 + warpCol + ni * 8 + 2 * tg;
            #pragma unroll
            for (int mi = 0; mi < 2; mi++) {
                int r0 = m0 + warpRow + mi * 16 + g;
                int r1 = r0 + 8;
                if (r0 < NN)
                    *(__half2*)&Y[(size_t)r0 * YN + col] =
                        __floats2half2_rn(acc[mi][ni][0], acc[mi][ni][1]);
                if (r1 < NN)
                    *(__half2*)&Y[(size_t)r1 * YN + col] =
                        __floats2half2_rn(acc[mi][ni][2], acc[mi][ni][3]);
            }
        }
        __syncthreads();
    }
}

// =====================================================================
// aggregation: warp per dst node, 16 lanes per edge (2 edges concurrent),
// 4-pair unroll -> 8 edges in flight at 4 loads/lane.
// =====================================================================
__device__ __forceinline__ void acc_u4(float* acc, uint4 u, float wgt) {
    float2 a0 = __half22float2(*(__half2*)&u.x);
    float2 a1 = __half22float2(*(__half2*)&u.y);
    float2 a2 = __half22float2(*(__half2*)&u.z);
    float2 a3 = __half22float2(*(__half2*)&u.w);
    acc[0] += wgt * a0.x; acc[1] += wgt * a0.y;
    acc[2] += wgt * a1.x; acc[3] += wgt * a1.y;
    acc[4] += wgt * a2.x; acc[5] += wgt * a2.y;
    acc[6] += wgt * a3.x; acc[7] += wgt * a3.y;
}

__global__ __launch_bounds__(256) void k_agg(const float* __restrict__ bias,
                                             float* __restrict__ out) {
    int w = (blockIdx.x * blockDim.x + threadIdx.x) >> 5;
    int lane = threadIdx.x & 31;
    if (w >= NN) return;
    int half = lane >> 4;      // which edge of the pair
    int hl = lane & 15;        // channel group (8 channels each)

    float wreg = (lane < RR) ? g_winv[w * RR + lane] : 1.0f;

    float acc[8];
    if (half == 0) {
        uint4 ru = *((const uint4*)(g_Yh + (size_t)w * YN + K1) + hl);
        float2 f0 = __half22float2(*(__half2*)&ru.x);
        float2 f1 = __half22float2(*(__half2*)&ru.y);
        float2 f2 = __half22float2(*(__half2*)&ru.z);
        float2 f3 = __half22float2(*(__half2*)&ru.w);
        float4 bv0 = *(const float4*)(bias + hl * 8);
        float4 bv1 = *(const float4*)(bias + hl * 8 + 4);
        acc[0] = f0.x + bv0.x; acc[1] = f0.y + bv0.y;
        acc[2] = f1.x + bv0.z; acc[3] = f1.y + bv0.w;
        acc[4] = f2.x + bv1.x; acc[5] = f2.y + bv1.y;
        acc[6] = f3.x + bv1.z; acc[7] = f3.y + bv1.w;
    } else {
        #pragma unroll
        for (int q = 0; q < 8; q++) acc[q] = 0.f;
    }

    int s = g_rowptr[w];
    int d = g_deg[w];
    int i = 0;
    for (; i + 8 <= d; i += 8) {
        int rec[4];
        #pragma unroll
        for (int p = 0; p < 4; p++) rec[p] = g_edge[s + i + 2 * p + half];
        uint4 u[4];
        #pragma unroll
        for (int p = 0; p < 4; p++)
            u[p] = *((const uint4*)(g_Yh + (size_t)(rec[p] & 0xFFFFF) * YN
                                    + (rec[p] >> 20) * CC) + hl);
        #pragma unroll
        for (int p = 0; p < 4; p++) {
            float wgt = __shfl_sync(0xFFFFFFFFu, wreg, rec[p] >> 20);
            acc_u4(acc, u[p], wgt);
        }
    }
    for (; i + 2 <= d; i += 2) {
        int rec = g_edge[s + i + half];
        uint4 u = *((const uint4*)(g_Yh + (size_t)(rec & 0xFFFFF) * YN
                                   + (rec >> 20) * CC) + hl);
        float wgt = __shfl_sync(0xFFFFFFFFu, wreg, rec >> 20);
        acc_u4(acc, u, wgt);
    }
    if (i < d) {   // odd tail: only half 0 takes it
        int rec = g_edge[s + i];
        float wgt = __shfl_sync(0xFFFFFFFFu, wreg, rec >> 20);
        if (half == 0) {
            uint4 u = *((const uint4*)(g_Yh + (size_t)(rec & 0xFFFFF) * YN
                                       + (rec >> 20) * CC) + hl);
            acc_u4(acc, u, wgt);
        }
    }

    // combine the two halves
    #pragma unroll
    for (int q = 0; q < 8; q++)
        acc[q] += __shfl_xor_sync(0xFFFFFFFFu, acc[q], 16);

    if (half == 0) {
        *(float4*)(out + (size_t)w * CC + hl * 8) =
            make_float4(acc[0], acc[1], acc[2], acc[3]);
        *(float4*)(out + (size_t)w * CC + hl * 8 + 4) =
            make_float4(acc[4], acc[5], acc[6], acc[7]);
    }
}

// ---------------- BatchNorm ----------------
__global__ void k_bnstats(const float* __restrict__ h) {
    int tid = threadIdx.x;
    int c = tid & (CC - 1);
    int half = tid >> 7;
    float s = 0.f, q = 0.f;
    for (int row = blockIdx.x * 2 + half; row < NN; row += gridDim.x * 2) {
        float v = h[(size_t)row * CC + c];
        s += v; q += v * v;
    }
    __shared__ float sh[256], shq[256];
    sh[tid] = s; shq[tid] = q;
    __syncthreads();
    if (tid < CC) {
        atomicAdd(&g_bnsum[c], sh[tid] + sh[tid + CC]);
        atomicAdd(&g_bnsq[c],  shq[tid] + shq[tid + CC]);
    }
}
__global__ void k_bnfinal(const float* __restrict__ bnw, const float* __restrict__ bnb) {
    int c = threadIdx.x;
    if (c >= CC) return;
    float mu = g_bnsum[c] / (float)NN;
    float var = g_bnsq[c] / (float)NN - mu * mu;
    float sc = bnw[c] * rsqrtf(var + EPS);
    g_scale[c] = sc;
    g_shift[c] = bnb[c] - mu * sc;
}
// BN apply + ReLU, writes fp16 A operand for layer-2 GEMM
__global__ void k_bnapply_pack(const float* __restrict__ h) {
    int i = blockIdx.x * blockDim.x + threadIdx.x;   // float2 units
    if (i >= NN * 64) return;
    int c2 = i & 63;
    float2 v = ((const float2*)h)[i];
    float2 sc = ((const float2*)g_scale)[c2];
    float2 sf = ((const float2*)g_shift)[c2];
    float a0 = fmaxf(0.f, v.x * sc.x + sf.x);
    float a1 = fmaxf(0.f, v.y * sc.y + sf.y);
    __half2 p = __floats2half2_rn(a0, a1);
    g_ax[i] = *(uint32_t*)&p;
}

// ---------------- edge_attr passthrough ----------------
__global__ void k_copyattr(const float* __restrict__ ea, float* __restrict__ out) {
    size_t i = (size_t)blockIdx.x * blockDim.x + threadIdx.x;
    size_t tot = (size_t)EE * 8 / 4;
    if (i < tot) ((float4*)out)[i] = ((const float4*)ea)[i];
}

// ---------------- launch ----------------
extern "C" void kernel_launch(void* const* d_in, const int* in_sizes, int n_in,
                              void* d_out, int out_size) {
    const float* x     = (const float*)d_in[0];
    const int*   ei    = (const int*)d_in[1];
    const float* eattr = (const float*)d_in[2];
    const int*   et    = (const int*)d_in[3];
    const float* W1    = (const float*)d_in[4];
    const float* root1 = (const float*)d_in[5];
    const float* b1    = (const float*)d_in[6];
    const float* bnw   = (const float*)d_in[7];
    const float* bnb   = (const float*)d_in[8];
    const float* W2    = (const float*)d_in[9];
    const float* root2 = (const float*)d_in[10];
    const float* b2    = (const float*)d_in[11];
    float* out = (float*)d_out;

    float* h;  cudaGetSymbolAddress((void**)&h, g_h);
    __half* Y; cudaGetSymbolAddress((void**)&Y, g_Yh);
    uint32_t* ax; cudaGetSymbolAddress((void**)&ax, g_ax);
    __half* bh; cudaGetSymbolAddress((void**)&bh, g_bh);

    static bool configured = false;
    if (!configured) {
        cudaFuncSetAttribute(k_gemm, cudaFuncAttributeMaxDynamicSharedMemorySize, GEMM_SMEM);
        configured = true;
    }

    const int T = 256;
    int blksNR   = (NN * RR + T - 1) / T;
    int blksE    = (EE + T - 1) / T;
    int blksN    = (NN + T - 1) / T;
    int blksPack = (YN * CC + T - 1) / T;
    int blksSpl  = (NN * 64 + T - 1) / T;
    int blksGemm = (NN + 127) / 128;
    int blksAgg  = (NN * 32 + T - 1) / T;
    int blksAttr = (int)(((size_t)EE * 8 / 4 + T - 1) / T);

    // structure prep (shared by both layers)
    k_init<<<blksNR, T>>>();
    k_count<<<blksE, T>>>(ei, et);
    k_winv_deg<<<blksN, T>>>();
    k_scan1<<<49, 1024>>>();
    k_scan2<<<1, 32>>>();
    k_scan3<<<blksN, T>>>();
    k_place<<<blksE, T>>>(ei, et);

    // operand prep
    k_packB<<<blksPack, T>>>(W1, root1, bh);
    k_packB<<<blksPack, T>>>(W2, root2, bh + (size_t)YN * CC);
    k_packX<<<blksSpl, T>>>(x);

    // ----- layer 1 -----
    k_gemm<<<blksGemm, 256, GEMM_SMEM>>>((__half*)ax, bh, Y);
    k_agg<<<blksAgg, T>>>(b1, h);
    k_bnstats<<<512, 256>>>(h);
    k_bnfinal<<<1, 128>>>(bnw, bnb);
    k_bnapply_pack<<<blksSpl, T>>>(h);

    // ----- layer 2 -----
    k_gemm<<<blksGemm, 256, GEMM_SMEM>>>((__half*)ax, bh + (size_t)YN * CC, Y);
    k_agg<<<blksAgg, T>>>(b2, out);

    // tuple second element
    k_copyattr<<<blksAttr, T>>>(eattr, out + (size_t)NN * CC);
}

// round 14
// speedup vs baseline: 1.0711x; 1.0711x over previous
#include <cuda_runtime.h>
#include <cuda_fp16.h>
#include <cstdint>

#define NN 50000
#define EE 800000
#define RR 16
#define CC 128
#define K1 2048            // R*C
#define YN 2176            // K1 + C  (Y = X @ [W_all | root])
#define NT 17              // YN / 128 n-tiles
#define EPS 1e-5f

// smem geometry for GEMM tiles: 128 x 136 fp16 (word stride 68 -> conflict-free)
#define ABYTES (128 * 136 * 2)     // 34816 bytes per tile array
#define GEMM_SMEM (3 * ABYTES)     // A + 2 stages x B = 104448

// ---------------- scratch ----------------
__device__ __half    g_Yh[(size_t)NN * YN];  // transformed features (fp16)
__device__ float    g_h[(size_t)NN * CC];    // hidden activations (pre-BN)
__device__ uint32_t g_ax[NN * 64];           // A operand fp16 (pairs), 256B rows
__device__ __half   g_bh[2 * YN * CC];       // packed B fp16 (both layers), [n][k]
__device__ int   g_cnt[NN * RR];
__device__ float g_winv[NN * RR];
__device__ int   g_deg[NN];
__device__ int   g_rowptr[NN];
__device__ int   g_cursor[NN];
__device__ int   g_bsumscan[64];
__device__ int   g_edge[EE];                 // sorted-by-dst: src | (rel<<20)
__device__ float g_bnsum[CC];
__device__ float g_bnsq[CC];
__device__ float g_scale[CC];
__device__ float g_shift[CC];

// ---------------- small helpers ----------------
__device__ __forceinline__ void cp16(uint32_t dst, const void* src) {
    asm volatile("cp.async.cg.shared.global [%0], [%1], 16;" :: "r"(dst), "l"(src));
}
__device__ __forceinline__ void cp_commit() { asm volatile("cp.async.commit_group;"); }

__device__ __forceinline__ void mma16816h(float* c, const uint32_t* a, const uint32_t* b) {
    asm volatile("mma.sync.aligned.m16n8k16.row.col.f32.f16.f16.f32 "
        "{%0,%1,%2,%3}, {%4,%5,%6,%7}, {%8,%9}, {%0,%1,%2,%3};"
        : "+f"(c[0]), "+f"(c[1]), "+f"(c[2]), "+f"(c[3])
        : "r"(a[0]), "r"(a[1]), "r"(a[2]), "r"(a[3]), "r"(b[0]), "r"(b[1]));
}

// ---------------- structure prep ----------------
__global__ void k_init() {
    int i = blockIdx.x * blockDim.x + threadIdx.x;
    if (i < NN * RR) g_cnt[i] = 0;
    if (i < CC) { g_bnsum[i] = 0.f; g_bnsq[i] = 0.f; }
}
__global__ void k_count(const int* __restrict__ ei, const int* __restrict__ et) {
    int e = blockIdx.x * blockDim.x + threadIdx.x;
    if (e >= EE) return;
    int dst = ei[EE + e];
    int r = et[e]; if (r > RR - 1) r = RR - 1;
    atomicAdd(&g_cnt[dst * RR + r], 1);
}
__global__ void k_winv_deg() {
    int n = blockIdx.x * blockDim.x + threadIdx.x;
    if (n >= NN) return;
    int d = 0;
    #pragma unroll
    for (int r = 0; r < RR; r++) {
        int c = g_cnt[n * RR + r];
        d += c;
        g_winv[n * RR + r] = 1.0f / (float)(c > 0 ? c : 1);
    }
    g_deg[n] = d;
}
__global__ void k_scan1() {   // 49 blocks x 1024
    __shared__ int sh[1024];
    int t = threadIdx.x;
    int idx = blockIdx.x * 1024 + t;
    int v = (idx < NN) ? g_deg[idx] : 0;
    sh[t] = v;
    __syncthreads();
    for (int o = 1; o < 1024; o <<= 1) {
        int add = (t >= o) ? sh[t - o] : 0;
        __syncthreads();
        sh[t] += add;
        __syncthreads();
    }
    if (idx < NN) g_rowptr[idx] = sh[t] - v;
    if (t == 1023) g_bsumscan[blockIdx.x] = sh[t];
}
__global__ void k_scan2() {
    if (threadIdx.x == 0) {
        int acc = 0;
        for (int b = 0; b < 49; b++) { int v = g_bsumscan[b]; g_bsumscan[b] = acc; acc += v; }
    }
}
__global__ void k_scan3() {
    int idx = blockIdx.x * blockDim.x + threadIdx.x;
    if (idx >= NN) return;
    int p = g_rowptr[idx] + g_bsumscan[idx >> 10];
    g_rowptr[idx] = p;
    g_cursor[idx] = p;
}
__global__ void k_place(const int* __restrict__ ei, const int* __restrict__ et) {
    int e = blockIdx.x * blockDim.x + threadIdx.x;
    if (e >= EE) return;
    int src = ei[e];
    int dst = ei[EE + e];
    int r = et[e]; if (r > RR - 1) r = RR - 1;
    int pos = atomicAdd(&g_cursor[dst], 1);
    g_edge[pos] = src | (r << 20);
}

// ---------------- operand prep ----------------
__global__ void k_packB(const float* __restrict__ W, const float* __restrict__ root,
                        __half* __restrict__ bh) {
    int idx = blockIdx.x * blockDim.x + threadIdx.x;   // n*128 + k
    if (idx >= YN * CC) return;
    int n = idx >> 7, k = idx & 127;
    float v = (n < K1) ? W[((size_t)(n >> 7) << 14) + (k << 7) + (n & 127)]
                       : root[(k << 7) + (n - K1)];
    bh[idx] = __float2half_rn(v);
}
__global__ void k_packX(const float* __restrict__ x) {
    int i = blockIdx.x * blockDim.x + threadIdx.x;     // float2 units
    if (i >= NN * 64) return;
    float2 v = ((const float2*)x)[i];
    __half2 h = __floats2half2_rn(v.x, v.y);
    g_ax[i] = *(uint32_t*)&h;
}

// =====================================================================
// GEMM: Y[N, 2176] = A[N,128] @ B^T   (fp16 x fp16, fp32 accum)
// =====================================================================
__global__ __launch_bounds__(256, 2) void k_gemm(
    const __half* __restrict__ Ahg,
    const __half* __restrict__ Bhg,   // [2176][128] n-major
    __half* __restrict__ Y)
{
    extern __shared__ char smem[];
    const int tid = threadIdx.x, lane = tid & 31, wid = tid >> 5;
    const int g = lane >> 2, tg = lane & 3;
    const int warpRow = (wid & 3) * 32, warpCol = (wid >> 2) * 64;
    const int m0 = blockIdx.x * 128;
    uint32_t sb = (uint32_t)__cvta_generic_to_shared(smem);

    #pragma unroll
    for (int it = 0; it < 8; it++) {
        int c = tid + it * 256;
        int row = c >> 4, chk = c & 15;
        int gr = m0 + row;
        if (gr >= NN) gr = NN - 1;
        size_t off = (size_t)gr * CC + chk * 8;
        cp16(sb + row * 272 + chk * 16, Ahg + off);
    }
    auto loadB = [&](int stage, int nt) {
        uint32_t bb = sb + ABYTES + stage * ABYTES;
        #pragma unroll
        for (int it = 0; it < 8; it++) {
            int c = tid + it * 256;
            int row = c >> 4, chk = c & 15;
            size_t goff = (size_t)(nt * CC + row) * CC + chk * 8;
            cp16(bb + row * 272 + chk * 16, Bhg + goff);
        }
    };
    loadB(0, 0);
    cp_commit();

    const uint32_t* A32 = (const uint32_t*)smem;

    for (int nt = 0; nt < NT; nt++) {
        int cur = nt & 1;
        if (nt + 1 < NT) {
            loadB(cur ^ 1, nt + 1);
            cp_commit();
            asm volatile("cp.async.wait_group 1;");
        } else {
            asm volatile("cp.async.wait_group 0;");
        }
        __syncthreads();

        const uint32_t* B32 = (const uint32_t*)(smem + ABYTES + cur * ABYTES);

        float acc[2][8][4];
        #pragma unroll
        for (int mi = 0; mi < 2; mi++)
            #pragma unroll
            for (int ni = 0; ni < 8; ni++)
                #pragma unroll
                for (int q = 0; q < 4; q++) acc[mi][ni][q] = 0.f;

        #pragma unroll
        for (int ks = 0; ks < 8; ks++) {
            int kp = ks * 8;
            uint32_t ah[2][4];
            #pragma unroll
            for (int mi = 0; mi < 2; mi++) {
                int r = warpRow + mi * 16 + g;
                ah[mi][0] = A32[r * 68 + kp + tg];
                ah[mi][1] = A32[(r + 8) * 68 + kp + tg];
                ah[mi][2] = A32[r * 68 + kp + tg + 4];
                ah[mi][3] = A32[(r + 8) * 68 + kp + tg + 4];
            }
            #pragma unroll
            for (int ni = 0; ni < 8; ni++) {
                int n = warpCol + ni * 8 + g;
                uint32_t bh[2] = { B32[n * 68 + kp + tg], B32[n * 68 + kp + tg + 4] };
                mma16816h(acc[0][ni], ah[0], bh);
                mma16816h(acc[1][ni], ah[1], bh);
            }
        }

        #pragma unroll
        for (int ni = 0; ni < 8; ni++) {
            int col = nt * 128 + warpCol + ni * 8 + 2 * tg;
            #pragma unroll
            for (int mi = 0; mi < 2; mi++) {
                int r0 = m0 + warpRow + mi * 16 + g;
                int r1 = r0 + 8;
                if (r0 < NN)
                    *(__half2*)&Y[(size_t)r0 * YN + col] =
                        __floats2half2_rn(acc[mi][ni][0], acc[mi][ni][1]);
                if (r1 < NN)
                    *(__half2*)&Y[(size_t)r1 * YN + col] =
                        __floats2half2_rn(acc[mi][ni][2], acc[mi][ni][3]);
            }
        }
        __syncthreads();
    }
}

// ---------------- aggregation: warp per dst node, MLP-4 pipelined gather ----------------
__global__ __launch_bounds__(256) void k_agg(const float* __restrict__ bias,
                                             float* __restrict__ out) {
    int w = (blockIdx.x * blockDim.x + threadIdx.x) >> 5;
    int lane = threadIdx.x & 31;
    if (w >= NN) return;

    float wreg = (lane < RR) ? g_winv[w * RR + lane] : 1.0f;

    uint2 ru = *(const uint2*)(g_Yh + (size_t)w * YN + K1 + lane * 4);
    float2 r0 = __half22float2(*(__half2*)&ru.x);
    float2 r1 = __half22float2(*(__half2*)&ru.y);
    float4 bv = *(const float4*)(bias + lane * 4);
    float4 acc = make_float4(r0.x + bv.x, r0.y + bv.y, r1.x + bv.z, r1.y + bv.w);

    int s = g_rowptr[w];
    int d = g_deg[w];
    int i = 0;
    for (; i + 4 <= d; i += 4) {
        int rec0 = g_edge[s + i], rec1 = g_edge[s + i + 1];
        int rec2 = g_edge[s + i + 2], rec3 = g_edge[s + i + 3];
        const uint2* p0 = (const uint2*)(g_Yh + (size_t)(rec0 & 0xFFFFF) * YN + (rec0 >> 20) * CC) + lane;
        const uint2* p1 = (const uint2*)(g_Yh + (size_t)(rec1 & 0xFFFFF) * YN + (rec1 >> 20) * CC) + lane;
        const uint2* p2 = (const uint2*)(g_Yh + (size_t)(rec2 & 0xFFFFF) * YN + (rec2 >> 20) * CC) + lane;
        const uint2* p3 = (const uint2*)(g_Yh + (size_t)(rec3 & 0xFFFFF) * YN + (rec3 >> 20) * CC) + lane;
        uint2 u0 = *p0, u1 = *p1, u2 = *p2, u3 = *p3;
        float w0 = __shfl_sync(0xFFFFFFFFu, wreg, rec0 >> 20);
        float w1 = __shfl_sync(0xFFFFFFFFu, wreg, rec1 >> 20);
        float w2 = __shfl_sync(0xFFFFFFFFu, wreg, rec2 >> 20);
        float w3 = __shfl_sync(0xFFFFFFFFu, wreg, rec3 >> 20);
        float2 a, b;
        a = __half22float2(*(__half2*)&u0.x); b = __half22float2(*(__half2*)&u0.y);
        acc.x += w0 * a.x; acc.y += w0 * a.y; acc.z += w0 * b.x; acc.w += w0 * b.y;
        a = __half22float2(*(__half2*)&u1.x); b = __half22float2(*(__half2*)&u1.y);
        acc.x += w1 * a.x; acc.y += w1 * a.y; acc.z += w1 * b.x; acc.w += w1 * b.y;
        a = __half22float2(*(__half2*)&u2.x); b = __half22float2(*(__half2*)&u2.y);
        acc.x += w2 * a.x; acc.y += w2 * a.y; acc.z += w2 * b.x; acc.w += w2 * b.y;
        a = __half22float2(*(__half2*)&u3.x); b = __half22float2(*(__half2*)&u3.y);
        acc.x += w3 * a.x; acc.y += w3 * a.y; acc.z += w3 * b.x; acc.w += w3 * b.y;
    }
    for (; i < d; i++) {
        int rec = g_edge[s + i];
        float wgt = __shfl_sync(0xFFFFFFFFu, wreg, rec >> 20);
        uint2 u = *((const uint2*)(g_Yh + (size_t)(rec & 0xFFFFF) * YN + (rec >> 20) * CC) + lane);
        float2 a = __half22float2(*(__half2*)&u.x);
        float2 b = __half22float2(*(__half2*)&u.y);
        acc.x += wgt * a.x; acc.y += wgt * a.y; acc.z += wgt * b.x; acc.w += wgt * b.y;
    }
    *(float4*)(out + (size_t)w * CC + lane * 4) = acc;
}

// ---------------- BatchNorm ----------------
__global__ void k_bnstats(const float* __restrict__ h) {
    int tid = threadIdx.x;
    int c = tid & (CC - 1);
    int half = tid >> 7;
    float s = 0.f, q = 0.f;
    for (int row = blockIdx.x * 2 + half; row < NN; row += gridDim.x * 2) {
        float v = h[(size_t)row * CC + c];
        s += v; q += v * v;
    }
    __shared__ float sh[256], shq[256];
    sh[tid] = s; shq[tid] = q;
    __syncthreads();
    if (tid < CC) {
        atomicAdd(&g_bnsum[c], sh[tid] + sh[tid + CC]);
        atomicAdd(&g_bnsq[c],  shq[tid] + shq[tid + CC]);
    }
}
__global__ void k_bnfinal(const float* __restrict__ bnw, const float* __restrict__ bnb) {
    int c = threadIdx.x;
    if (c >= CC) return;
    float mu = g_bnsum[c] / (float)NN;
    float var = g_bnsq[c] / (float)NN - mu * mu;
    float sc = bnw[c] * rsqrtf(var + EPS);
    g_scale[c] = sc;
    g_shift[c] = bnb[c] - mu * sc;
}
// BN apply + ReLU, writes fp16 A operand for layer-2 GEMM
__global__ void k_bnapply_pack(const float* __restrict__ h) {
    int i = blockIdx.x * blockDim.x + threadIdx.x;   // float2 units
    if (i >= NN * 64) return;
    int c2 = i & 63;
    float2 v = ((const float2*)h)[i];
    float2 sc = ((const float2*)g_scale)[c2];
    float2 sf = ((const float2*)g_shift)[c2];
    float a0 = fmaxf(0.f, v.x * sc.x + sf.x);
    float a1 = fmaxf(0.f, v.y * sc.y + sf.y);
    __half2 p = __floats2half2_rn(a0, a1);
    g_ax[i] = *(uint32_t*)&p;
}

// ---------------- edge_attr passthrough ----------------
__global__ void k_copyattr(const float* __restrict__ ea, float* __restrict__ out) {
    size_t i = (size_t)blockIdx.x * blockDim.x + threadIdx.x;
    size_t tot = (size_t)EE * 8 / 4;
    if (i < tot) ((float4*)out)[i] = ((const float4*)ea)[i];
}

// ---------------- launch ----------------
extern "C" void kernel_launch(void* const* d_in, const int* in_sizes, int n_in,
                              void* d_out, int out_size) {
    const float* x     = (const float*)d_in[0];
    const int*   ei    = (const int*)d_in[1];
    const float* eattr = (const float*)d_in[2];
    const int*   et    = (const int*)d_in[3];
    const float* W1    = (const float*)d_in[4];
    const float* root1 = (const float*)d_in[5];
    const float* b1    = (const float*)d_in[6];
    const float* bnw   = (const float*)d_in[7];
    const float* bnb   = (const float*)d_in[8];
    const float* W2    = (const float*)d_in[9];
    const float* root2 = (const float*)d_in[10];
    const float* b2    = (const float*)d_in[11];
    float* out = (float*)d_out;

    float* h;  cudaGetSymbolAddress((void**)&h, g_h);
    __half* Y; cudaGetSymbolAddress((void**)&Y, g_Yh);
    uint32_t* ax; cudaGetSymbolAddress((void**)&ax, g_ax);
    __half* bh; cudaGetSymbolAddress((void**)&bh, g_bh);

    static cudaStream_t s2;
    static cudaEvent_t evFork, evJoin;
    static bool configured = false;
    if (!configured) {
        cudaFuncSetAttribute(k_gemm, cudaFuncAttributeMaxDynamicSharedMemorySize, GEMM_SMEM);
        cudaStreamCreateWithFlags(&s2, cudaStreamNonBlocking);
        cudaEventCreateWithFlags(&evFork, cudaEventDisableTiming);
        cudaEventCreateWithFlags(&evJoin, cudaEventDisableTiming);
        configured = true;
    }

    const int T = 256;
    int blksNR   = (NN * RR + T - 1) / T;
    int blksE    = (EE + T - 1) / T;
    int blksN    = (NN + T - 1) / T;
    int blksPack = (YN * CC + T - 1) / T;
    int blksSpl  = (NN * 64 + T - 1) / T;
    int blksGemm = (NN + 127) / 128;
    int blksAgg  = (NN * 32 + T - 1) / T;
    int blksAttr = (int)(((size_t)EE * 8 / 4 + T - 1) / T);

    // fork: side branch does structure prep + layer-2 packB + edge_attr copy
    cudaEventRecord(evFork, 0);
    cudaStreamWaitEvent(s2, evFork, 0);
    k_init<<<blksNR, T, 0, s2>>>();
    k_count<<<blksE, T, 0, s2>>>(ei, et);
    k_winv_deg<<<blksN, T, 0, s2>>>();
    k_scan1<<<49, 1024, 0, s2>>>();
    k_scan2<<<1, 32, 0, s2>>>();
    k_scan3<<<blksN, T, 0, s2>>>();
    k_place<<<blksE, T, 0, s2>>>(ei, et);
    k_packB<<<blksPack, T, 0, s2>>>(W2, root2, bh + (size_t)YN * CC);
    k_copyattr<<<blksAttr, T, 0, s2>>>(eattr, out + (size_t)NN * CC);
    cudaEventRecord(evJoin, s2);

    // main branch: layer-1 operand prep + GEMM (independent of structure)
    k_packB<<<blksPack, T>>>(W1, root1, bh);
    k_packX<<<blksSpl, T>>>(x);
    k_gemm<<<blksGemm, 256, GEMM_SMEM>>>((__half*)ax, bh, Y);

    // join before aggregation (needs CSR + counts)
    cudaStreamWaitEvent(0, evJoin, 0);

    // ----- layer 1 -----
    k_agg<<<blksAgg, T>>>(b1, h);
    k_bnstats<<<512, 256>>>(h);
    k_bnfinal<<<1, 128>>>(bnw, bnb);
    k_bnapply_pack<<<blksSpl, T>>>(h);

    // ----- layer 2 -----
    k_gemm<<<blksGemm, 256, GEMM_SMEM>>>((__half*)ax, bh + (size_t)YN * CC, Y);
    k_agg<<<blksAgg, T>>>(b2, out);
}

// round 15
// speedup vs baseline: 1.0885x; 1.0163x over previous
#include <cuda_runtime.h>
#include <cuda_fp16.h>
#include <cstdint>

#define NN 50000
#define EE 800000
#define RR 16
#define CC 128
#define K1 2048            // R*C
#define YN 2176            // K1 + C  (Y = X @ [W_all | root])
#define NT 17              // YN / 128 n-tiles
#define EPS 1e-5f

// smem geometry for GEMM tiles: 128 x 136 fp16 (word stride 68 -> conflict-free)
#define ABYTES (128 * 136 * 2)     // 34816 bytes per tile array
#define GEMM_SMEM (3 * ABYTES)     // A + 2 stages x B = 104448

// ---------------- scratch ----------------
__device__ __half    g_Yh[(size_t)NN * YN];  // transformed features (fp16)
__device__ float    g_h[(size_t)NN * CC];    // hidden activations (pre-BN)
__device__ uint32_t g_ax[NN * 64];           // A operand fp16 (pairs), 256B rows
__device__ __half   g_bh[2 * YN * CC];       // packed B fp16 (both layers), [n][k]
__device__ int   g_cnt[NN * RR];
__device__ float g_winv[NN * RR];
__device__ int   g_deg[NN];
__device__ int   g_rowptr[NN];
__device__ int   g_cursor[NN];
__device__ int   g_bsumscan[64];
__device__ int   g_edge[EE];                 // sorted-by-dst: src | (rel<<20)
__device__ float g_bnsum[CC];
__device__ float g_bnsq[CC];
__device__ float g_scale[CC];
__device__ float g_shift[CC];
__device__ int   g_bnctr;

// ---------------- small helpers ----------------
__device__ __forceinline__ void cp16(uint32_t dst, const void* src) {
    asm volatile("cp.async.cg.shared.global [%0], [%1], 16;" :: "r"(dst), "l"(src));
}
__device__ __forceinline__ void cp_commit() { asm volatile("cp.async.commit_group;"); }

__device__ __forceinline__ void mma16816h(float* c, const uint32_t* a, const uint32_t* b) {
    asm volatile("mma.sync.aligned.m16n8k16.row.col.f32.f16.f16.f32 "
        "{%0,%1,%2,%3}, {%4,%5,%6,%7}, {%8,%9}, {%0,%1,%2,%3};"
        : "+f"(c[0]), "+f"(c[1]), "+f"(c[2]), "+f"(c[3])
        : "r"(a[0]), "r"(a[1]), "r"(a[2]), "r"(a[3]), "r"(b[0]), "r"(b[1]));
}

// ---------------- structure prep ----------------
__global__ void k_init() {
    int i = blockIdx.x * blockDim.x + threadIdx.x;
    if (i < NN * RR) g_cnt[i] = 0;
    if (i < CC) { g_bnsum[i] = 0.f; g_bnsq[i] = 0.f; }
    if (i == 0) g_bnctr = 0;
}
__global__ void k_count(const int* __restrict__ ei, const int* __restrict__ et) {
    int e = blockIdx.x * blockDim.x + threadIdx.x;
    if (e >= EE) return;
    int dst = ei[EE + e];
    int r = et[e]; if (r > RR - 1) r = RR - 1;
    atomicAdd(&g_cnt[dst * RR + r], 1);
}
__global__ void k_winv_deg() {
    int n = blockIdx.x * blockDim.x + threadIdx.x;
    if (n >= NN) return;
    int d = 0;
    #pragma unroll
    for (int r = 0; r < RR; r++) {
        int c = g_cnt[n * RR + r];
        d += c;
        g_winv[n * RR + r] = 1.0f / (float)(c > 0 ? c : 1);
    }
    g_deg[n] = d;
}
__global__ void k_scan1() {   // 49 blocks x 1024
    __shared__ int sh[1024];
    int t = threadIdx.x;
    int idx = blockIdx.x * 1024 + t;
    int v = (idx < NN) ? g_deg[idx] : 0;
    sh[t] = v;
    __syncthreads();
    for (int o = 1; o < 1024; o <<= 1) {
        int add = (t >= o) ? sh[t - o] : 0;
        __syncthreads();
        sh[t] += add;
        __syncthreads();
    }
    if (idx < NN) g_rowptr[idx] = sh[t] - v;
    if (t == 1023) g_bsumscan[blockIdx.x] = sh[t];
}
__global__ void k_scan2() {
    if (threadIdx.x == 0) {
        int acc = 0;
        for (int b = 0; b < 49; b++) { int v = g_bsumscan[b]; g_bsumscan[b] = acc; acc += v; }
    }
}
__global__ void k_scan3() {
    int idx = blockIdx.x * blockDim.x + threadIdx.x;
    if (idx >= NN) return;
    int p = g_rowptr[idx] + g_bsumscan[idx >> 10];
    g_rowptr[idx] = p;
    g_cursor[idx] = p;
}
__global__ void k_place(const int* __restrict__ ei, const int* __restrict__ et) {
    int e = blockIdx.x * blockDim.x + threadIdx.x;
    if (e >= EE) return;
    int src = ei[e];
    int dst = ei[EE + e];
    int r = et[e]; if (r > RR - 1) r = RR - 1;
    int pos = atomicAdd(&g_cursor[dst], 1);
    g_edge[pos] = src | (r << 20);
}

// ---------------- operand prep ----------------
__global__ void k_packB(const float* __restrict__ W, const float* __restrict__ root,
                        __half* __restrict__ bh) {
    int idx = blockIdx.x * blockDim.x + threadIdx.x;   // n*128 + k
    if (idx >= YN * CC) return;
    int n = idx >> 7, k = idx & 127;
    float v = (n < K1) ? W[((size_t)(n >> 7) << 14) + (k << 7) + (n & 127)]
                       : root[(k << 7) + (n - K1)];
    bh[idx] = __float2half_rn(v);
}
__global__ void k_packX(const float* __restrict__ x) {
    int i = blockIdx.x * blockDim.x + threadIdx.x;     // float2 units
    if (i >= NN * 64) return;
    float2 v = ((const float2*)x)[i];
    __half2 h = __floats2half2_rn(v.x, v.y);
    g_ax[i] = *(uint32_t*)&h;
}

// =====================================================================
// GEMM: Y[N, 2176] = A[N,128] @ B^T   (fp16 x fp16, fp32 accum)
// FUSE_BN: A loaded as fp32 from Hsrc, BN scale/shift + ReLU applied,
// converted to fp16 in the prologue (replaces the separate bnapply pass).
// =====================================================================
template<bool FUSE_BN>
__global__ __launch_bounds__(256, 2) void k_gemm_t(
    const __half* __restrict__ Ahg,
    const float* __restrict__ Hsrc,
    const __half* __restrict__ Bhg,   // [2176][128] n-major
    __half* __restrict__ Y)
{
    extern __shared__ char smem[];
    const int tid = threadIdx.x, lane = tid & 31, wid = tid >> 5;
    const int g = lane >> 2, tg = lane & 3;
    const int warpRow = (wid & 3) * 32, warpCol = (wid >> 2) * 64;
    const int m0 = blockIdx.x * 128;
    uint32_t sb = (uint32_t)__cvta_generic_to_shared(smem);

    if (!FUSE_BN) {
        #pragma unroll
        for (int it = 0; it < 8; it++) {
            int c = tid + it * 256;
            int row = c >> 4, chk = c & 15;
            int gr = m0 + row;
            if (gr >= NN) gr = NN - 1;
            size_t off = (size_t)gr * CC + chk * 8;
            cp16(sb + row * 272 + chk * 16, Ahg + off);
        }
    } else {
        #pragma unroll
        for (int it = 0; it < 8; it++) {
            int c = tid + it * 256;
            int row = c >> 4, chk = c & 15;
            int gr = m0 + row;
            if (gr >= NN) gr = NN - 1;
            const float4* hp = (const float4*)(Hsrc + (size_t)gr * CC + chk * 8);
            float4 v0 = hp[0], v1 = hp[1];
            float4 sc0 = *(const float4*)(g_scale + chk * 8);
            float4 sc1 = *(const float4*)(g_scale + chk * 8 + 4);
            float4 sf0 = *(const float4*)(g_shift + chk * 8);
            float4 sf1 = *(const float4*)(g_shift + chk * 8 + 4);
            float a0 = fmaxf(0.f, v0.x * sc0.x + sf0.x);
            float a1 = fmaxf(0.f, v0.y * sc0.y + sf0.y);
            float a2 = fmaxf(0.f, v0.z * sc0.z + sf0.z);
            float a3 = fmaxf(0.f, v0.w * sc0.w + sf0.w);
            float a4 = fmaxf(0.f, v1.x * sc1.x + sf1.x);
            float a5 = fmaxf(0.f, v1.y * sc1.y + sf1.y);
            float a6 = fmaxf(0.f, v1.z * sc1.z + sf1.z);
            float a7 = fmaxf(0.f, v1.w * sc1.w + sf1.w);
            __half2 h0 = __floats2half2_rn(a0, a1);
            __half2 h1 = __floats2half2_rn(a2, a3);
            __half2 h2 = __floats2half2_rn(a4, a5);
            __half2 h3 = __floats2half2_rn(a6, a7);
            uint4 pk = make_uint4(*(uint32_t*)&h0, *(uint32_t*)&h1,
                                  *(uint32_t*)&h2, *(uint32_t*)&h3);
            *(uint4*)(smem + row * 272 + chk * 16) = pk;
        }
    }
    auto loadB = [&](int stage, int nt) {
        uint32_t bb = sb + ABYTES + stage * ABYTES;
        #pragma unroll
        for (int it = 0; it < 8; it++) {
            int c = tid + it * 256;
            int row = c >> 4, chk = c & 15;
            size_t goff = (size_t)(nt * CC + row) * CC + chk * 8;
            cp16(bb + row * 272 + chk * 16, Bhg + goff);
        }
    };
    loadB(0, 0);
    cp_commit();

    const uint32_t* A32 = (const uint32_t*)smem;

    for (int nt = 0; nt < NT; nt++) {
        int cur = nt & 1;
        if (nt + 1 < NT) {
            loadB(cur ^ 1, nt + 1);
            cp_commit();
            asm volatile("cp.async.wait_group 1;");
        } else {
            asm volatile("cp.async.wait_group 0;");
        }
        __syncthreads();

        const uint32_t* B32 = (const uint32_t*)(smem + ABYTES + cur * ABYTES);

        float acc[2][8][4];
        #pragma unroll
        for (int mi = 0; mi < 2; mi++)
            #pragma unroll
            for (int ni = 0; ni < 8; ni++)
                #pragma unroll
                for (int q = 0; q < 4; q++) acc[mi][ni][q] = 0.f;

        #pragma unroll
        for (int ks = 0; ks < 8; ks++) {
            int kp = ks * 8;
            uint32_t ah[2][4];
            #pragma unroll
            for (int mi = 0; mi < 2; mi++) {
                int r = warpRow + mi * 16 + g;
                ah[mi][0] = A32[r * 68 + kp + tg];
                ah[mi][1] = A32[(r + 8) * 68 + kp + tg];
                ah[mi][2] = A32[r * 68 + kp + tg + 4];
                ah[mi][3] = A32[(r + 8) * 68 + kp + tg + 4];
            }
            #pragma unroll
            for (int ni = 0; ni < 8; ni++) {
                int n = warpCol + ni * 8 + g;
                uint32_t bh[2] = { B32[n * 68 + kp + tg], B32[n * 68 + kp + tg + 4] };
                mma16816h(acc[0][ni], ah[0], bh);
                mma16816h(acc[1][ni], ah[1], bh);
            }
        }

        #pragma unroll
        for (int ni = 0; ni < 8; ni++) {
            int col = nt * 128 + warpCol + ni * 8 + 2 * tg;
            #pragma unroll
            for (int mi = 0; mi < 2; mi++) {
                int r0 = m0 + warpRow + mi * 16 + g;
                int r1 = r0 + 8;
                if (r0 < NN)
                    *(__half2*)&Y[(size_t)r0 * YN + col] =
                        __floats2half2_rn(acc[mi][ni][0], acc[mi][ni][1]);
                if (r1 < NN)
                    *(__half2*)&Y[(size_t)r1 * YN + col] =
                        __floats2half2_rn(acc[mi][ni][2], acc[mi][ni][3]);
            }
        }
        __syncthreads();
    }
}

// ---------------- aggregation: warp per dst node, MLP-4 pipelined gather ----------------
__global__ __launch_bounds__(256) void k_agg(const float* __restrict__ bias,
                                             float* __restrict__ out) {
    int w = (blockIdx.x * blockDim.x + threadIdx.x) >> 5;
    int lane = threadIdx.x & 31;
    if (w >= NN) return;

    float wreg = (lane < RR) ? g_winv[w * RR + lane] : 1.0f;

    uint2 ru = *(const uint2*)(g_Yh + (size_t)w * YN + K1 + lane * 4);
    float2 r0 = __half22float2(*(__half2*)&ru.x);
    float2 r1 = __half22float2(*(__half2*)&ru.y);
    float4 bv = *(const float4*)(bias + lane * 4);
    float4 acc = make_float4(r0.x + bv.x, r0.y + bv.y, r1.x + bv.z, r1.y + bv.w);

    int s = g_rowptr[w];
    int d = g_deg[w];
    int i = 0;
    for (; i + 4 <= d; i += 4) {
        int rec0 = g_edge[s + i], rec1 = g_edge[s + i + 1];
        int rec2 = g_edge[s + i + 2], rec3 = g_edge[s + i + 3];
        const uint2* p0 = (const uint2*)(g_Yh + (size_t)(rec0 & 0xFFFFF) * YN + (rec0 >> 20) * CC) + lane;
        const uint2* p1 = (const uint2*)(g_Yh + (size_t)(rec1 & 0xFFFFF) * YN + (rec1 >> 20) * CC) + lane;
        const uint2* p2 = (const uint2*)(g_Yh + (size_t)(rec2 & 0xFFFFF) * YN + (rec2 >> 20) * CC) + lane;
        const uint2* p3 = (const uint2*)(g_Yh + (size_t)(rec3 & 0xFFFFF) * YN + (rec3 >> 20) * CC) + lane;
        uint2 u0 = *p0, u1 = *p1, u2 = *p2, u3 = *p3;
        float w0 = __shfl_sync(0xFFFFFFFFu, wreg, rec0 >> 20);
        float w1 = __shfl_sync(0xFFFFFFFFu, wreg, rec1 >> 20);
        float w2 = __shfl_sync(0xFFFFFFFFu, wreg, rec2 >> 20);
        float w3 = __shfl_sync(0xFFFFFFFFu, wreg, rec3 >> 20);
        float2 a, b;
        a = __half22float2(*(__half2*)&u0.x); b = __half22float2(*(__half2*)&u0.y);
        acc.x += w0 * a.x; acc.y += w0 * a.y; acc.z += w0 * b.x; acc.w += w0 * b.y;
        a = __half22float2(*(__half2*)&u1.x); b = __half22float2(*(__half2*)&u1.y);
        acc.x += w1 * a.x; acc.y += w1 * a.y; acc.z += w1 * b.x; acc.w += w1 * b.y;
        a = __half22float2(*(__half2*)&u2.x); b = __half22float2(*(__half2*)&u2.y);
        acc.x += w2 * a.x; acc.y += w2 * a.y; acc.z += w2 * b.x; acc.w += w2 * b.y;
        a = __half22float2(*(__half2*)&u3.x); b = __half22float2(*(__half2*)&u3.y);
        acc.x += w3 * a.x; acc.y += w3 * a.y; acc.z += w3 * b.x; acc.w += w3 * b.y;
    }
    for (; i < d; i++) {
        int rec = g_edge[s + i];
        float wgt = __shfl_sync(0xFFFFFFFFu, wreg, rec >> 20);
        uint2 u = *((const uint2*)(g_Yh + (size_t)(rec & 0xFFFFF) * YN + (rec >> 20) * CC) + lane);
        float2 a = __half22float2(*(__half2*)&u.x);
        float2 b = __half22float2(*(__half2*)&u.y);
        acc.x += wgt * a.x; acc.y += wgt * a.y; acc.z += wgt * b.x; acc.w += wgt * b.y;
    }
    *(float4*)(out + (size_t)w * CC + lane * 4) = acc;
}

// ---------------- BatchNorm: stats + fused final (last block) ----------------
__global__ void k_bnstats(const float* __restrict__ h,
                          const float* __restrict__ bnw, const float* __restrict__ bnb) {
    int tid = threadIdx.x;
    int c = tid & (CC - 1);
    int half = tid >> 7;
    float s = 0.f, q = 0.f;
    for (int row = blockIdx.x * 2 + half; row < NN; row += gridDim.x * 2) {
        float v = h[(size_t)row * CC + c];
        s += v; q += v * v;
    }
    __shared__ float sh[256], shq[256];
    sh[tid] = s; shq[tid] = q;
    __syncthreads();
    if (tid < CC) {
        atomicAdd(&g_bnsum[c], sh[tid] + sh[tid + CC]);
        atomicAdd(&g_bnsq[c],  shq[tid] + shq[tid + CC]);
    }
    __threadfence();
    __syncthreads();
    __shared__ int isLast;
    if (tid == 0) isLast = (atomicAdd(&g_bnctr, 1) == (int)gridDim.x - 1);
    __syncthreads();
    if (isLast && tid < CC) {
        float su = atomicAdd(&g_bnsum[tid], 0.f);
        float qu = atomicAdd(&g_bnsq[tid], 0.f);
        float mu = su / (float)NN;
        float var = qu / (float)NN - mu * mu;
        float sc = bnw[tid] * rsqrtf(var + EPS);
        g_scale[tid] = sc;
        g_shift[tid] = bnb[tid] - mu * sc;
    }
}

// ---------------- edge_attr passthrough ----------------
__global__ void k_copyattr(const float* __restrict__ ea, float* __restrict__ out) {
    size_t i = (size_t)blockIdx.x * blockDim.x + threadIdx.x;
    size_t tot = (size_t)EE * 8 / 4;
    if (i < tot) ((float4*)out)[i] = ((const float4*)ea)[i];
}

// ---------------- launch ----------------
extern "C" void kernel_launch(void* const* d_in, const int* in_sizes, int n_in,
                              void* d_out, int out_size) {
    const float* x     = (const float*)d_in[0];
    const int*   ei    = (const int*)d_in[1];
    const float* eattr = (const float*)d_in[2];
    const int*   et    = (const int*)d_in[3];
    const float* W1    = (const float*)d_in[4];
    const float* root1 = (const float*)d_in[5];
    const float* b1    = (const float*)d_in[6];
    const float* bnw   = (const float*)d_in[7];
    const float* bnb   = (const float*)d_in[8];
    const float* W2    = (const float*)d_in[9];
    const float* root2 = (const float*)d_in[10];
    const float* b2    = (const float*)d_in[11];
    float* out = (float*)d_out;

    float* h;  cudaGetSymbolAddress((void**)&h, g_h);
    __half* Y; cudaGetSymbolAddress((void**)&Y, g_Yh);
    uint32_t* ax; cudaGetSymbolAddress((void**)&ax, g_ax);
    __half* bh; cudaGetSymbolAddress((void**)&bh, g_bh);

    static cudaStream_t s2;
    static cudaEvent_t evFork, evJoin;
    static bool configured = false;
    if (!configured) {
        cudaFuncSetAttribute(k_gemm_t<false>, cudaFuncAttributeMaxDynamicSharedMemorySize, GEMM_SMEM);
        cudaFuncSetAttribute(k_gemm_t<true>,  cudaFuncAttributeMaxDynamicSharedMemorySize, GEMM_SMEM);
        cudaStreamCreateWithFlags(&s2, cudaStreamNonBlocking);
        cudaEventCreateWithFlags(&evFork, cudaEventDisableTiming);
        cudaEventCreateWithFlags(&evJoin, cudaEventDisableTiming);
        configured = true;
    }

    const int T = 256;
    int blksNR   = (NN * RR + T - 1) / T;
    int blksE    = (EE + T - 1) / T;
    int blksN    = (NN + T - 1) / T;
    int blksPack = (YN * CC + T - 1) / T;
    int blksSpl  = (NN * 64 + T - 1) / T;
    int blksGemm = (NN + 127) / 128;
    int blksAgg  = (NN * 32 + T - 1) / T;
    int blksAttr = (int)(((size_t)EE * 8 / 4 + T - 1) / T);

    // fork: side branch does structure prep + layer-2 packB + edge_attr copy
    cudaEventRecord(evFork, 0);
    cudaStreamWaitEvent(s2, evFork, 0);
    k_init<<<blksNR, T, 0, s2>>>();
    k_count<<<blksE, T, 0, s2>>>(ei, et);
    k_winv_deg<<<blksN, T, 0, s2>>>();
    k_scan1<<<49, 1024, 0, s2>>>();
    k_scan2<<<1, 32, 0, s2>>>();
    k_scan3<<<blksN, T, 0, s2>>>();
    k_place<<<blksE, T, 0, s2>>>(ei, et);
    k_packB<<<blksPack, T, 0, s2>>>(W2, root2, bh + (size_t)YN * CC);
    k_copyattr<<<blksAttr, T, 0, s2>>>(eattr, out + (size_t)NN * CC);
    cudaEventRecord(evJoin, s2);

    // main branch: layer-1 operand prep + GEMM (independent of structure)
    k_packB<<<blksPack, T>>>(W1, root1, bh);
    k_packX<<<blksSpl, T>>>(x);
    k_gemm_t<false><<<blksGemm, 256, GEMM_SMEM>>>((__half*)ax, nullptr, bh, Y);

    // join before aggregation (needs CSR + counts + bn init)
    cudaStreamWaitEvent(0, evJoin, 0);

    // ----- layer 1 -----
    k_agg<<<blksAgg, T>>>(b1, h);
    k_bnstats<<<512, 256>>>(h, bnw, bnb);

    // ----- layer 2 (BN apply fused into GEMM A-prologue) -----
    k_gemm_t<true><<<blksGemm, 256, GEMM_SMEM>>>(nullptr, h, bh + (size_t)YN * CC, Y);
    k_agg<<<blksAgg, T>>>(b2, out);
}